// round 13
// baseline (speedup 1.0000x reference)
#include <cuda_runtime.h>
#include <math.h>
#include <stdint.h>

#define DIMC 512
#define IDIM 1024
#define BATCH 8
#define TLEN 1024
#define NC 128            // RNN CTAs
#define NCPAD 8           // flag padding (32B) to spread L2 sectors

typedef unsigned long long u64;

// ---------------- scratch (device globals; no allocation allowed) ----------------
__device__ float g_H [BATCH*DIMC*TLEN];   // conv0+gelu out   [b][d][t]
__device__ float g_Z [BATCH*TLEN*IDIM];   // join out         [b][t][i]
__device__ float g_U0[TLEN*BATCH*IDIM];   // u0 (+b_ih0+b_hh0)[t][b][j]
__device__ float g_Yr[BATCH*TLEN*IDIM];   // rnn out          [b][t][j]
__device__ float g_Y2[BATCH*TLEN*IDIM];   // u1 out           [b][t][i]
__device__ float g_Y3[BATCH*DIMC*TLEN];   // u2 out           [b][d][t]
__device__ float g_h0x[2][BATCH*IDIM];    // h0 exchange, double buffered [b][i]
__device__ float g_h1x[2][BATCH*IDIM];    // h1 exchange, double buffered [b][i]
__device__ unsigned g_flag0[NC*NCPAD];    // per-CTA h0-publish epoch
__device__ unsigned g_flag1[NC*NCPAD];    // per-CTA h1-publish epoch

// ---------------- packed f32x2 helpers (bitwise == 2 scalar rn FMAs) --------------
#define FFMA2(d,a,b) asm("fma.rn.f32x2 %0, %1, %2, %0;" : "+l"(d) : "l"(a), "l"(b))

__device__ __forceinline__ u64 dup2(float x) {
    u64 d; unsigned xi = __float_as_uint(x);
    asm("mov.b64 %0, {%1, %1};" : "=l"(d) : "r"(xi));
    return d;
}
__device__ __forceinline__ void unpack2(u64 v, float& lo, float& hi) {
    unsigned a, b;
    asm("mov.b64 {%0, %1}, %2;" : "=r"(a), "=r"(b) : "l"(v));
    lo = __uint_as_float(a); hi = __uint_as_float(b);
}

// ---------------- acquire/release message passing ----------------
__device__ __forceinline__ unsigned ld_acq(const unsigned* p) {
    unsigned v;
    asm volatile("ld.acquire.gpu.global.u32 %0, [%1];" : "=r"(v) : "l"(p) : "memory");
    return v;
}
__device__ __forceinline__ void st_rel(unsigned* p, unsigned v) {
    asm volatile("st.release.gpu.global.u32 [%0], %1;" :: "l"(p), "r"(v) : "memory");
}

// ---------------- cp.async helpers ----------------
__device__ __forceinline__ void cp_async16(uint32_t saddr, const void* gptr) {
    asm volatile("cp.async.cg.shared.global [%0], [%1], 16;" :: "r"(saddr), "l"(gptr));
}
#define CP_COMMIT() asm volatile("cp.async.commit_group;" ::: "memory")
#define CP_WAIT0()  asm volatile("cp.async.wait_group 0;" ::: "memory")

#define BAR1() asm volatile("bar.sync 1, 128;" ::: "memory")
#define BAR2() asm volatile("bar.sync 2, 128;" ::: "memory")

__device__ __forceinline__ float gelu_f(float x) {
    return 0.5f * x * (1.0f + erff(x * 0.7071067811865476f));
}

// ---------------- flag reset (graph replays reuse device globals) ----------------
__global__ void zero_flags_kernel() {
    int i = blockIdx.x * 256 + threadIdx.x;
    if (i < NC * NCPAD) { g_flag0[i] = 0; g_flag1[i] = 0; }
}

// ---------------- depthwise conv (7 tap, pad 3) + optional gelu/residual ----------------
__global__ void dwconv_kernel(const float* __restrict__ in, const float* __restrict__ w,
                              const float* __restrict__ bias, const float* __restrict__ resid,
                              float* __restrict__ out, int do_gelu)
{
    int bd = blockIdx.x;            // b*DIMC + d
    int d  = bd % DIMC;
    __shared__ float s[TLEN + 6];
    const float* row = in + (size_t)bd * TLEN;
    for (int t = threadIdx.x; t < TLEN; t += blockDim.x) s[t + 3] = row[t];
    if (threadIdx.x < 3) { s[threadIdx.x] = 0.0f; s[TLEN + 3 + threadIdx.x] = 0.0f; }
    __syncthreads();
    float wr[7];
#pragma unroll
    for (int k = 0; k < 7; k++) wr[k] = w[d * 7 + k];
    float bb = bias[d];
    for (int t = threadIdx.x; t < TLEN; t += blockDim.x) {
        float acc = bb;
#pragma unroll
        for (int k = 0; k < 7; k++) acc += s[t + k] * wr[k];
        if (do_gelu) acc = gelu_f(acc);
        if (resid)   acc += resid[(size_t)bd * TLEN + t];
        out[(size_t)bd * TLEN + t] = acc;
    }
}

// ---------------- tiled SGEMM, round-9 winner: 128x64, 4x4-pair f32x2 ------------
#define BM 128
#define BN 64
#define BK 16

template<bool A_COL, bool DO_GELU, bool STORE_T>
__global__ __launch_bounds__(256)
void sgemm_kernel(const float* __restrict__ A, const float* __restrict__ B,
                  const float* __restrict__ bias, const float* __restrict__ bias2,
                  float* __restrict__ C,
                  int M, int N, int K, int lda,
                  long strideA, long strideC, int ldc)
{
    A += (long)blockIdx.z * strideA;
    C += (long)blockIdx.z * strideC;
    int m0 = blockIdx.y * BM;
    int n0 = blockIdx.x * BN;

    __shared__ float As[BK][BM + 4];
    __shared__ float Bs[BK][BN + 4];

    int tid = threadIdx.x;
    int tx = tid & 15;
    int ty = tid >> 4;

    u64 acc2[4][4];
#pragma unroll
    for (int i = 0; i < 4; i++)
#pragma unroll
        for (int j = 0; j < 4; j++) acc2[i][j] = 0ULL;

    for (int k0 = 0; k0 < K; k0 += BK) {
        if (A_COL) {
            int kk = tid >> 4;
            int mm = (tid & 15) * 8;
            const float4* src = (const float4*)(A + (size_t)(k0 + kk) * lda + m0 + mm);
            float4 v0 = src[0], v1 = src[1];
            *(float4*)&As[kk][mm]     = v0;
            *(float4*)&As[kk][mm + 4] = v1;
        } else {
            int mm = tid >> 1;
            int kk = (tid & 1) * 8;
            const float4* src = (const float4*)(A + (size_t)(m0 + mm) * lda + k0 + kk);
            float4 v0 = src[0], v1 = src[1];
            As[kk + 0][mm] = v0.x; As[kk + 1][mm] = v0.y; As[kk + 2][mm] = v0.z; As[kk + 3][mm] = v0.w;
            As[kk + 4][mm] = v1.x; As[kk + 5][mm] = v1.y; As[kk + 6][mm] = v1.z; As[kk + 7][mm] = v1.w;
        }
        {
            int nn = tid >> 2;
            int kk = (tid & 3) * 4;
            float4 v = *(const float4*)(B + (size_t)(n0 + nn) * K + k0 + kk);
            Bs[kk + 0][nn] = v.x; Bs[kk + 1][nn] = v.y; Bs[kk + 2][nn] = v.z; Bs[kk + 3][nn] = v.w;
        }
        __syncthreads();

#pragma unroll
        for (int k = 0; k < BK; k++) {
            ulonglong2 p0 = *(const ulonglong2*)&As[k][ty * 8];
            ulonglong2 p1 = *(const ulonglong2*)&As[k][ty * 8 + 4];
            u64 ap[4] = {p0.x, p0.y, p1.x, p1.y};
            float4 b0 = *(const float4*)&Bs[k][tx * 4];
            u64 bd[4] = {dup2(b0.x), dup2(b0.y), dup2(b0.z), dup2(b0.w)};
#pragma unroll
            for (int i = 0; i < 4; i++)
#pragma unroll
                for (int j = 0; j < 4; j++) FFMA2(acc2[i][j], ap[i], bd[j]);
        }
        __syncthreads();
    }

#pragma unroll
    for (int j = 0; j < 4; j++) {
        int n = n0 + tx * 4 + j;
        float bv = bias[n];
        if (bias2) bv += bias2[n];
#pragma unroll
        for (int i = 0; i < 4; i++) {
            float vlo, vhi;
            unpack2(acc2[i][j], vlo, vhi);
            int m = m0 + ty * 8 + 2 * i;
            float a = vlo + bv, b = vhi + bv;
            if (DO_GELU) { a = gelu_f(a); b = gelu_f(b); }
            if (STORE_T) { C[(size_t)n * ldc + m] = a; C[(size_t)n * ldc + m + 1] = b; }
            else         { C[(size_t)m * ldc + n] = a; C[(size_t)(m + 1) * ldc + n] = b; }
        }
    }
}

// ---------------- persistent RNN kernel: split-flag early-publish pipeline --------
// smem: h0s[8192] + h1s[8192] ([b][i]) + pf[512]
//   pf[0..127]   : Whh0 partials, warp wq in 0..3 at pf[wq*32]
//   pf[128..255] : Whh1 partials, warp wq at pf[128+wq*32]
//   pf[256..511] : Wih1 partials, warp w at pf[256+w*32]
// Epochs:
//   flags0: prefill=1; slot t publishes t+2 (h0(t) published, slot-t h0-read done)
//   flags1: prefill=1; slot t publishes t+2 (slot t fully done, incl. h1-read)
//   h0 gate at slot t: flags0 >= t+1   (h0(t-1) available; WAR-safe)
//   h1 gate at slot t: flags1 >= (t==0 ? 1 : t+1)
//     t>=2: h1(t-2) published at end of slot t-1 (=t+1); t>=1: WAR for combine
//     overwriting the buffer read at slot t-1 (needs slot t-1 fully done = t+1).
#define RNN_SMEM_FLOATS (IDIM*16 + 512)

// butterfly reduce (verified rounds 7-11)
__device__ __forceinline__ float bfly_reduce32(float* a, int lane) {
#pragma unroll
    for (int p = 0; p < 16; p++) {
        bool up = (lane & 16) != 0;
        float send = up ? a[p] : a[p + 16];
        float keep = up ? a[p + 16] : a[p];
        a[p] = keep + __shfl_xor_sync(0xffffffffu, send, 16);
    }
#pragma unroll
    for (int p = 0; p < 8; p++) {
        bool up = (lane & 8) != 0;
        float send = up ? a[p] : a[p + 8];
        float keep = up ? a[p + 8] : a[p];
        a[p] = keep + __shfl_xor_sync(0xffffffffu, send, 8);
    }
#pragma unroll
    for (int p = 0; p < 4; p++) {
        bool up = (lane & 4) != 0;
        float send = up ? a[p] : a[p + 4];
        float keep = up ? a[p + 4] : a[p];
        a[p] = keep + __shfl_xor_sync(0xffffffffu, send, 4);
    }
#pragma unroll
    for (int p = 0; p < 2; p++) {
        bool up = (lane & 2) != 0;
        float send = up ? a[p] : a[p + 2];
        float keep = up ? a[p + 2] : a[p];
        a[p] = keep + __shfl_xor_sync(0xffffffffu, send, 2);
    }
    {
        bool up = (lane & 1) != 0;
        float send = up ? a[0] : a[1];
        float keep = up ? a[1] : a[0];
        a[0] = keep + __shfl_xor_sync(0xffffffffu, send, 1);
    }
    return a[0];
}

__global__ __launch_bounds__(256, 1)
void rnn_kernel(const float* __restrict__ U0,     // [t][b][j], includes b_ih0+b_hh0
                const float* __restrict__ Whh0,
                const float* __restrict__ Wih1,
                const float* __restrict__ Whh1,
                const float* __restrict__ bih1,
                const float* __restrict__ bhh1,
                const float* __restrict__ starter, // [2][IDIM]
                float* __restrict__ Y)             // [b][t][j]
{
    extern __shared__ float sm[];
    float* h0s = sm;                    // [b][i]
    float* h1s = sm + IDIM * 8;
    float* pf  = sm + IDIM * 16;

    int tid  = threadIdx.x;
    int lane = tid & 31;
    int warp = tid >> 5;
    int row0 = blockIdx.x * 8;
    int cta  = blockIdx.x;

    uint32_t h0sa = (uint32_t)__cvta_generic_to_shared(h0s);
    uint32_t h1sa = (uint32_t)__cvta_generic_to_shared(h1s);

    // ---- A-weight preload: warps 0-3 -> Whh0, warps 4-7 -> Whh1 ----
    int wq  = warp & 3;                 // 0..3 within group
    int mat = warp >> 2;                // 0: Whh0 group, 1: Whh1 group
    int gA  = wq & 1;
    int kcA = wq >> 1;
    int kbA = kcA * 512;
    const float* WAm = mat ? Whh1 : Whh0;
    ulonglong2 wA[4][4];
#pragma unroll
    for (int grp = 0; grp < 4; grp++)
#pragma unroll
        for (int r = 0; r < 4; r++)
            wA[grp][r] = *(const ulonglong2*)&WAm[(size_t)(row0 + gA * 4 + r) * IDIM
                                                  + kbA + grp * 128 + lane * 4];

    // ---- Wih1 preload (all warps): g=warp&1, kc=warp>>1 ----
    int gB  = warp & 1;
    int kcB = warp >> 1;
    int kbB = kcB * 256;
    ulonglong2 wB[2][4];
#pragma unroll
    for (int grp = 0; grp < 2; grp++)
#pragma unroll
        for (int r = 0; r < 4; r++)
            wB[grp][r] = *(const ulonglong2*)&Wih1[(size_t)(row0 + gB * 4 + r) * IDIM
                                                   + kbB + grp * 128 + lane * 4];

    // combine-thread params
    int cmb_b  = tid & 7;
    int cmb_jl = (tid & 63) >> 3;
    int cmb_j  = row0 + cmb_jl;
    float cbias = 0.0f;
    if (tid >= 64 && tid < 128) cbias = bih1[cmb_j] + bhh1[cmb_j];

    // ---- prefill exchange buffers with starter state; publish epoch 1 ----
    if (tid < 64) {
        float s0 = starter[cmb_j];
        float s1 = starter[IDIM + cmb_j];
        g_h0x[1][cmb_b * IDIM + cmb_j] = s0;   // h0(-1), read at slot 0 (parity 1)
        g_h1x[0][cmb_b * IDIM + cmb_j] = s1;   // h1(-2), read at slot 0 (parity 0)
        g_h1x[1][cmb_b * IDIM + cmb_j] = s1;   // h1(-1), read at slot 1 (parity 1)
    }
    __syncthreads();
    if (tid == 0) {
        __threadfence();
        st_rel(&g_flag0[cta * NCPAD], 1u);
        st_rel(&g_flag1[cta * NCPAD], 1u);
    }

    // ================= main loop: slot t computes h0(t) and h1(t-1) =================
    for (int t = 0; t <= TLEN; t++) {
        if (tid < 128) {
            // ======== H0 path (warps 0-3) ========
            {
                unsigned need = (unsigned)(t + 1);
                const unsigned* fp = &g_flag0[tid * NCPAD];
                while (ld_acq(fp) < need) { }
            }
            BAR1();
            // broadcast h0(t-1): 2048 float4 over 128 threads
            {
                const float4* s0 = (const float4*)g_h0x[(t + 1) & 1];
#pragma unroll
                for (int q = 0; q < 16; q++)
                    cp_async16(h0sa + (unsigned)(tid + q * 128) * 16u, s0 + tid + q * 128);
                CP_COMMIT();
            }
            float u0v = 0.0f;
            if (tid < 64 && t < TLEN)
                u0v = __ldcg(&U0[(size_t)t * (BATCH * IDIM) + (size_t)cmb_b * IDIM + cmb_j]);
            CP_WAIT0();
            BAR1();                     // h0s fully staged (group-local)

            // Whh0 dot: 4r x 8b x K512 (i-pair FFMA2)
            {
                u64 acc2[4][8];
#pragma unroll
                for (int r = 0; r < 4; r++)
#pragma unroll
                    for (int b = 0; b < 8; b++) acc2[r][b] = 0ULL;
#pragma unroll
                for (int grp = 0; grp < 4; grp++) {
                    int ib = kbA + grp * 128 + lane * 4;
                    ulonglong2 hp[8];
#pragma unroll
                    for (int b = 0; b < 8; b++)
                        hp[b] = *(const ulonglong2*)&h0s[b * 1024 + ib];
#pragma unroll
                    for (int r = 0; r < 4; r++) {
                        ulonglong2 wp = wA[grp][r];
#pragma unroll
                        for (int b = 0; b < 8; b++) {
                            FFMA2(acc2[r][b], hp[b].x, wp.x);
                            FFMA2(acc2[r][b], hp[b].y, wp.y);
                        }
                    }
                }
                float acc[32];
#pragma unroll
                for (int r = 0; r < 4; r++)
#pragma unroll
                    for (int b = 0; b < 8; b++) {
                        float lo, hi;
                        unpack2(acc2[r][b], lo, hi);
                        acc[r * 8 + b] = lo + hi;
                    }
                pf[wq * 32 + lane] = bfly_reduce32(acc, lane);
            }
            BAR1();

            // h0 combine + store + EARLY publish
            if (tid < 64 && t < TLEN) {
                int gg = cmb_jl >> 2, rr = cmb_jl & 3;
                int f = rr * 8 + cmb_b;
                float s = pf[gg * 32 + f] + pf[(gg + 2) * 32 + f];
                float hv = tanhf(u0v + s);
                g_h0x[t & 1][cmb_b * IDIM + cmb_j] = hv;
            }
            BAR1();
            if (tid == 0) {
                __threadfence();
                st_rel(&g_flag0[cta * NCPAD], (unsigned)(t + 2));
            }
        } else {
            // ======== H1 path (warps 4-7) ========
            int ptid = tid - 128;
            {
                unsigned need = (t == 0) ? 1u : (unsigned)(t + 1);
                const unsigned* fp = &g_flag1[ptid * NCPAD];
                while (ld_acq(fp) < need) { }
            }
            BAR2();
            // broadcast h1(t-2)
            {
                const float4* s1 = (const float4*)g_h1x[t & 1];
#pragma unroll
                for (int q = 0; q < 16; q++)
                    cp_async16(h1sa + (unsigned)(ptid + q * 128) * 16u, s1 + ptid + q * 128);
                CP_COMMIT();
            }
            CP_WAIT0();
            BAR2();                     // h1s fully staged (group-local)

            // Whh1 dot: 4r x 8b x K512
            {
                u64 acc2[4][8];
#pragma unroll
                for (int r = 0; r < 4; r++)
#pragma unroll
                    for (int b = 0; b < 8; b++) acc2[r][b] = 0ULL;
#pragma unroll
                for (int grp = 0; grp < 4; grp++) {
                    int ib = kbA + grp * 128 + lane * 4;
                    ulonglong2 hp[8];
#pragma unroll
                    for (int b = 0; b < 8; b++)
                        hp[b] = *(const ulonglong2*)&h1s[b * 1024 + ib];
#pragma unroll
                    for (int r = 0; r < 4; r++) {
                        ulonglong2 wp = wA[grp][r];
#pragma unroll
                        for (int b = 0; b < 8; b++) {
                            FFMA2(acc2[r][b], hp[b].x, wp.x);
                            FFMA2(acc2[r][b], hp[b].y, wp.y);
                        }
                    }
                }
                float acc[32];
#pragma unroll
                for (int r = 0; r < 4; r++)
#pragma unroll
                    for (int b = 0; b < 8; b++) {
                        float lo, hi;
                        unpack2(acc2[r][b], lo, hi);
                        acc[r * 8 + b] = lo + hi;
                    }
                pf[128 + wq * 32 + lane] = bfly_reduce32(acc, lane);
            }
        }
        __syncthreads();    // joins groups: h0s visible to warps 4-7, pf stores visible

        // ======== Wih1 (all warps): 4r x 8b x K256 on h0s ========
        {
            u64 acc2[4][8];
#pragma unroll
            for (int r = 0; r < 4; r++)
#pragma unroll
                for (int b = 0; b < 8; b++) acc2[r][b] = 0ULL;
#pragma unroll
            for (int grp = 0; grp < 2; grp++) {
                int ib = kbB + grp * 128 + lane * 4;
                ulonglong2 hp[8];
#pragma unroll
                for (int b = 0; b < 8; b++)
                    hp[b] = *(const ulonglong2*)&h0s[b * 1024 + ib];
#pragma unroll
                for (int r = 0; r < 4; r++) {
                    ulonglong2 wp = wB[grp][r];
#pragma unroll
                    for (int b = 0; b < 8; b++) {
                        FFMA2(acc2[r][b], hp[b].x, wp.x);
                        FFMA2(acc2[r][b], hp[b].y, wp.y);
                    }
                }
            }
            float acc[32];
#pragma unroll
            for (int r = 0; r < 4; r++)
#pragma unroll
                for (int b = 0; b < 8; b++) {
                    float lo, hi;
                    unpack2(acc2[r][b], lo, hi);
                    acc[r * 8 + b] = lo + hi;
                }
            pf[256 + warp * 32 + lane] = bfly_reduce32(acc, lane);
        }
        __syncthreads();

        // ======== h1(t-1) combine + publish ========
        if (tid >= 64 && tid < 128 && t >= 1) {
            int gg = cmb_jl >> 2, rr = cmb_jl & 3;
            int f = rr * 8 + cmb_b;
            float sA = pf[128 + gg * 32 + f] + pf[128 + (gg + 2) * 32 + f];
            float sB = pf[256 + (gg + 0) * 32 + f] + pf[256 + (gg + 2) * 32 + f]
                     + pf[256 + (gg + 4) * 32 + f] + pf[256 + (gg + 6) * 32 + f];
            float hv = tanhf(sA + sB + cbias);
            g_h1x[(t + 1) & 1][cmb_b * IDIM + cmb_j] = hv;
            Y[((size_t)cmb_b * TLEN + (t - 1)) * IDIM + cmb_j] = hv;
        }
        __syncthreads();
        if (tid == 0) {
            __threadfence();
            st_rel(&g_flag1[cta * NCPAD], (unsigned)(t + 2));
        }
    }
}

// ---------------- launch ----------------
extern "C" void kernel_launch(void* const* d_in, const int* in_sizes, int n_in,
                              void* d_out, int out_size)
{
    const float* x      = (const float*)d_in[0];
    const float* w_dw0  = (const float*)d_in[1];
    const float* b_dw0  = (const float*)d_in[2];
    const float* w_dw1  = (const float*)d_in[3];
    const float* b_dw1  = (const float*)d_in[4];
    const float* w_join = (const float*)d_in[5];
    const float* b_join = (const float*)d_in[6];
    const float* w_ih0  = (const float*)d_in[7];
    const float* w_hh0  = (const float*)d_in[8];
    const float* b_ih0  = (const float*)d_in[9];
    const float* b_hh0  = (const float*)d_in[10];
    const float* w_ih1  = (const float*)d_in[11];
    const float* w_hh1  = (const float*)d_in[12];
    const float* b_ih1  = (const float*)d_in[13];
    const float* b_hh1  = (const float*)d_in[14];
    const float* w_u1   = (const float*)d_in[15];
    const float* b_u1   = (const float*)d_in[16];
    const float* w_u2   = (const float*)d_in[17];
    const float* b_u2   = (const float*)d_in[18];
    const float* starter= (const float*)d_in[19];
    float* out = (float*)d_out;

    float *H, *Z, *U0, *Yr, *Y2, *Y3;
    cudaGetSymbolAddress((void**)&H,  g_H);
    cudaGetSymbolAddress((void**)&Z,  g_Z);
    cudaGetSymbolAddress((void**)&U0, g_U0);
    cudaGetSymbolAddress((void**)&Yr, g_Yr);
    cudaGetSymbolAddress((void**)&Y2, g_Y2);
    cudaGetSymbolAddress((void**)&Y3, g_Y3);

    // 0) reset RNN flags (graph replays reuse device globals)
    zero_flags_kernel<<<4, 256>>>();

    // 1) dwconv0 + gelu -> H [b][d][t]
    dwconv_kernel<<<BATCH * DIMC, 256>>>(x, w_dw0, b_dw0, nullptr, H, 1);

    // 2) join: Z[b][t][i] = H[b][:,t] . w_join[i,:] + b_join
    sgemm_kernel<true, false, false><<<dim3(IDIM / BN, TLEN / BM, BATCH), 256>>>(
        H, w_join, b_join, nullptr, Z,
        TLEN, IDIM, DIMC, TLEN, (long)DIMC * TLEN, (long)TLEN * IDIM, IDIM);

    // 3) u0: U0[t][b][j] = Z[b][t][:] . w_ih0[j,:] + b_ih0 + b_hh0
    sgemm_kernel<false, false, false><<<dim3(IDIM / BN, TLEN / BM, BATCH), 256>>>(
        Z, w_ih0, b_ih0, b_hh0, U0,
        TLEN, IDIM, IDIM, IDIM, (long)TLEN * IDIM, (long)IDIM, BATCH * IDIM);

    // 4) persistent RNN over T steps -> Yr [b][t][j]
    cudaFuncSetAttribute(rnn_kernel, cudaFuncAttributeMaxDynamicSharedMemorySize,
                         RNN_SMEM_FLOATS * (int)sizeof(float));
    rnn_kernel<<<NC, 256, RNN_SMEM_FLOATS * (int)sizeof(float)>>>(
        U0, w_hh0, w_ih1, w_hh1, b_ih1, b_hh1, starter, Yr);

    // 5) u1 + gelu
    sgemm_kernel<false, true, false><<<dim3(IDIM / BN, TLEN / BM, BATCH), 256>>>(
        Yr, w_u1, b_u1, nullptr, Y2,
        TLEN, IDIM, IDIM, IDIM, (long)TLEN * IDIM, (long)TLEN * IDIM, IDIM);

    // 6) u2 + gelu, transposed store: Y3[b][d][t]
    sgemm_kernel<false, true, true><<<dim3(DIMC / BN, TLEN / BM, BATCH), 256>>>(
        Y2, w_u2, b_u2, nullptr, Y3,
        TLEN, DIMC, IDIM, IDIM, (long)TLEN * IDIM, (long)DIMC * TLEN, TLEN);

    // 7) dwconv1 + bias + residual -> out [b][d][t]
    dwconv_kernel<<<BATCH * DIMC, 256>>>(Y3, w_dw1, b_dw1, x, out, 0);
}

// round 14
// speedup vs baseline: 1.0952x; 1.0952x over previous
#include <cuda_runtime.h>
#include <math.h>
#include <stdint.h>

#define DIMC 512
#define IDIM 1024
#define BATCH 8
#define TLEN 1024
#define NC 128            // RNN CTAs (8 leaves x 16)

typedef unsigned long long u64;

// ---------------- scratch (device globals; no allocation allowed) ----------------
__device__ float g_H [BATCH*DIMC*TLEN];   // conv0+gelu out   [b][d][t]
__device__ float g_Z [BATCH*TLEN*IDIM];   // join out         [b][t][i]
__device__ float g_U0[TLEN*BATCH*IDIM];   // u0 (+b_ih0+b_hh0)[t][b][j]
__device__ float g_Yr[BATCH*TLEN*IDIM];   // rnn out          [b][t][j]
__device__ float g_Y2[BATCH*TLEN*IDIM];   // u1 out           [b][t][i]
__device__ float g_Y3[BATCH*DIMC*TLEN];   // u2 out           [b][d][t]
__device__ float g_h0x[2][BATCH*IDIM];    // h0 exchange, double buffered [b][i]
__device__ float g_h1x[2][BATCH*IDIM];    // h1 exchange, double buffered [b][i]
__device__ unsigned g_l1[8*64];           // tree-barrier leaf counters (256B apart)
__device__ unsigned g_root;               // tree-barrier root counter
__device__ volatile unsigned g_gen2;      // completed-epoch generation (monotonic)

// ---------------- packed f32x2 helpers (GEMMs only; bitwise == 2 scalar FFMAs) ----
#define FFMA2(d,a,b) asm("fma.rn.f32x2 %0, %1, %2, %0;" : "+l"(d) : "l"(a), "l"(b))

__device__ __forceinline__ u64 dup2(float x) {
    u64 d; unsigned xi = __float_as_uint(x);
    asm("mov.b64 %0, {%1, %1};" : "=l"(d) : "r"(xi));
    return d;
}
__device__ __forceinline__ void unpack2(u64 v, float& lo, float& hi) {
    unsigned a, b;
    asm("mov.b64 {%0, %1}, %2;" : "=r"(a), "=r"(b) : "l"(v));
    lo = __uint_as_float(a); hi = __uint_as_float(b);
}

// ---------------- cp.async helpers (RNN broadcast) ----------------
__device__ __forceinline__ void cp_async16(uint32_t saddr, const void* gptr) {
    asm volatile("cp.async.cg.shared.global [%0], [%1], 16;" :: "r"(saddr), "l"(gptr));
}
#define CP_COMMIT() asm volatile("cp.async.commit_group;" ::: "memory")
#define CP_WAIT1()  asm volatile("cp.async.wait_group 1;" ::: "memory")
#define CP_WAIT0()  asm volatile("cp.async.wait_group 0;" ::: "memory")

__device__ __forceinline__ float gelu_f(float x) {
    return 0.5f * x * (1.0f + erff(x * 0.7071067811865476f));
}

// ---------------- barrier counter reset (graph replays reuse device globals) -----
__global__ void zero_tree_kernel() {
    int i = threadIdx.x;
    if (i < 8 * 64) g_l1[i] = 0;
    if (i == 0) { g_root = 0; g_gen2 = 0; }
}

// ---------------- depthwise conv (7 tap, pad 3) + optional gelu/residual ----------------
__global__ void dwconv_kernel(const float* __restrict__ in, const float* __restrict__ w,
                              const float* __restrict__ bias, const float* __restrict__ resid,
                              float* __restrict__ out, int do_gelu)
{
    int bd = blockIdx.x;            // b*DIMC + d
    int d  = bd % DIMC;
    __shared__ float s[TLEN + 6];
    const float* row = in + (size_t)bd * TLEN;
    for (int t = threadIdx.x; t < TLEN; t += blockDim.x) s[t + 3] = row[t];
    if (threadIdx.x < 3) { s[threadIdx.x] = 0.0f; s[TLEN + 3 + threadIdx.x] = 0.0f; }
    __syncthreads();
    float wr[7];
#pragma unroll
    for (int k = 0; k < 7; k++) wr[k] = w[d * 7 + k];
    float bb = bias[d];
    for (int t = threadIdx.x; t < TLEN; t += blockDim.x) {
        float acc = bb;
#pragma unroll
        for (int k = 0; k < 7; k++) acc += s[t + k] * wr[k];
        if (do_gelu) acc = gelu_f(acc);
        if (resid)   acc += resid[(size_t)bd * TLEN + t];
        out[(size_t)bd * TLEN + t] = acc;
    }
}

// ---------------- tiled SGEMM: register-staged pipeline, one sync/iter -----------
// 128x64 block, 4x4-pair f32x2 microtile (identical FFMA2 order to round-9 winner).
#define BM 128
#define BN 64
#define BK 16

template<bool A_COL, bool DO_GELU, bool STORE_T>
__global__ __launch_bounds__(256)
void sgemm_kernel(const float* __restrict__ A, const float* __restrict__ B,
                  const float* __restrict__ bias, const float* __restrict__ bias2,
                  float* __restrict__ C,
                  int M, int N, int K, int lda,
                  long strideA, long strideC, int ldc)
{
    A += (long)blockIdx.z * strideA;
    C += (long)blockIdx.z * strideC;
    int m0 = blockIdx.y * BM;
    int n0 = blockIdx.x * BN;

    __shared__ float As[2][BK][BM + 4];
    __shared__ float Bs[2][BK][BN + 4];

    int tid = threadIdx.x;
    int tx = tid & 15;
    int ty = tid >> 4;

    // loader coordinates
    int a_kk, a_mm;
    if (A_COL) { a_kk = tid >> 4; a_mm = (tid & 15) * 8; }
    else       { a_mm = tid >> 1; a_kk = (tid & 1) * 8;  }
    int b_nn = tid >> 2;
    int b_kk = (tid & 3) * 4;

    u64 acc2[4][4];
#pragma unroll
    for (int i = 0; i < 4; i++)
#pragma unroll
        for (int j = 0; j < 4; j++) acc2[i][j] = 0ULL;

    // ---- prologue: load tile 0 into registers ----
    float4 ra0, ra1, rb;
    {
        if (A_COL) {
            const float4* src = (const float4*)(A + (size_t)(0 + a_kk) * lda + m0 + a_mm);
            ra0 = src[0]; ra1 = src[1];
        } else {
            const float4* src = (const float4*)(A + (size_t)(m0 + a_mm) * lda + 0 + a_kk);
            ra0 = src[0]; ra1 = src[1];
        }
        rb = *(const float4*)(B + (size_t)(n0 + b_nn) * K + 0 + b_kk);
    }

    int nIter = K / BK;
    for (int it = 0; it < nIter; it++) {
        int s = it & 1;
        // ---- stage registers -> smem buffer s ----
        if (A_COL) {
            *(float4*)&As[s][a_kk][a_mm]     = ra0;
            *(float4*)&As[s][a_kk][a_mm + 4] = ra1;
        } else {
            As[s][a_kk + 0][a_mm] = ra0.x; As[s][a_kk + 1][a_mm] = ra0.y;
            As[s][a_kk + 2][a_mm] = ra0.z; As[s][a_kk + 3][a_mm] = ra0.w;
            As[s][a_kk + 4][a_mm] = ra1.x; As[s][a_kk + 5][a_mm] = ra1.y;
            As[s][a_kk + 6][a_mm] = ra1.z; As[s][a_kk + 7][a_mm] = ra1.w;
        }
        Bs[s][b_kk + 0][b_nn] = rb.x; Bs[s][b_kk + 1][b_nn] = rb.y;
        Bs[s][b_kk + 2][b_nn] = rb.z; Bs[s][b_kk + 3][b_nn] = rb.w;
        __syncthreads();

        // ---- prefetch next tile into registers (overlaps compute) ----
        if (it + 1 < nIter) {
            int k0 = (it + 1) * BK;
            if (A_COL) {
                const float4* src = (const float4*)(A + (size_t)(k0 + a_kk) * lda + m0 + a_mm);
                ra0 = src[0]; ra1 = src[1];
            } else {
                const float4* src = (const float4*)(A + (size_t)(m0 + a_mm) * lda + k0 + a_kk);
                ra0 = src[0]; ra1 = src[1];
            }
            rb = *(const float4*)(B + (size_t)(n0 + b_nn) * K + k0 + b_kk);
        }

        // ---- compute buffer s ----
#pragma unroll
        for (int k = 0; k < BK; k++) {
            ulonglong2 p0 = *(const ulonglong2*)&As[s][k][ty * 8];
            ulonglong2 p1 = *(const ulonglong2*)&As[s][k][ty * 8 + 4];
            u64 ap[4] = {p0.x, p0.y, p1.x, p1.y};
            float4 b0 = *(const float4*)&Bs[s][k][tx * 4];
            u64 bd[4] = {dup2(b0.x), dup2(b0.y), dup2(b0.z), dup2(b0.w)};
#pragma unroll
            for (int i = 0; i < 4; i++)
#pragma unroll
                for (int j = 0; j < 4; j++) FFMA2(acc2[i][j], ap[i], bd[j]);
        }
    }

#pragma unroll
    for (int j = 0; j < 4; j++) {
        int n = n0 + tx * 4 + j;
        float bv = bias[n];
        if (bias2) bv += bias2[n];
#pragma unroll
        for (int i = 0; i < 4; i++) {
            float vlo, vhi;
            unpack2(acc2[i][j], vlo, vhi);
            int m = m0 + ty * 8 + 2 * i;
            float a = vlo + bv, b = vhi + bv;
            if (DO_GELU) { a = gelu_f(a); b = gelu_f(b); }
            if (STORE_T) { C[(size_t)n * ldc + m] = a; C[(size_t)n * ldc + m + 1] = b; }
            else         { C[(size_t)m * ldc + n] = a; C[(size_t)(m + 1) * ldc + n] = b; }
        }
    }
}

// ---------------- persistent RNN kernel (round-9 winner, verbatim) ----------------
// smem: h0s[8192] + h1s[8192] ([b][i]) + pf[512] (A partials at 0, B partials at 256)
#define RNN_SMEM_FLOATS (IDIM*16 + 512)

// tree barrier, monotonic counters, epoch e >= 1
__device__ __forceinline__ void tree_sync(unsigned e)
{
    __syncthreads();
    if (threadIdx.x == 0) {
        __threadfence();
        unsigned grp = blockIdx.x & 7;               // 16 CTAs per leaf
        if (atomicAdd(&g_l1[grp * 64], 1u) == 16u * e - 1u) {
            if (atomicAdd(&g_root, 1u) == 8u * e - 1u) {
                __threadfence();
                g_gen2 = e;
            }
        }
        while (g_gen2 < e) { }
        __threadfence();
    }
    __syncthreads();
}

// recursive-halving butterfly: input a[32] (value id v = index); returns the full
// 32-lane sum of value id == lane. Masks 16,8,4,2,1 with position compaction.
__device__ __forceinline__ float bfly_reduce32(float* a, int lane) {
#pragma unroll
    for (int p = 0; p < 16; p++) {
        bool up = (lane & 16) != 0;
        float send = up ? a[p] : a[p + 16];
        float keep = up ? a[p + 16] : a[p];
        a[p] = keep + __shfl_xor_sync(0xffffffffu, send, 16);
    }
#pragma unroll
    for (int p = 0; p < 8; p++) {
        bool up = (lane & 8) != 0;
        float send = up ? a[p] : a[p + 8];
        float keep = up ? a[p + 8] : a[p];
        a[p] = keep + __shfl_xor_sync(0xffffffffu, send, 8);
    }
#pragma unroll
    for (int p = 0; p < 4; p++) {
        bool up = (lane & 4) != 0;
        float send = up ? a[p] : a[p + 4];
        float keep = up ? a[p + 4] : a[p];
        a[p] = keep + __shfl_xor_sync(0xffffffffu, send, 4);
    }
#pragma unroll
    for (int p = 0; p < 2; p++) {
        bool up = (lane & 2) != 0;
        float send = up ? a[p] : a[p + 2];
        float keep = up ? a[p + 2] : a[p];
        a[p] = keep + __shfl_xor_sync(0xffffffffu, send, 2);
    }
    {
        bool up = (lane & 1) != 0;
        float send = up ? a[0] : a[1];
        float keep = up ? a[1] : a[0];
        a[0] = keep + __shfl_xor_sync(0xffffffffu, send, 1);
    }
    return a[0];
}

__global__ __launch_bounds__(256, 1)
void rnn_kernel(const float* __restrict__ U0,     // [t][b][j], includes b_ih0+b_hh0
                const float* __restrict__ Whh0,
                const float* __restrict__ Wih1,
                const float* __restrict__ Whh1,
                const float* __restrict__ bih1,
                const float* __restrict__ bhh1,
                const float* __restrict__ starter, // [2][IDIM]
                float* __restrict__ Y)             // [b][t][j]
{
    extern __shared__ float sm[];
    float* h0s = sm;                    // [b][i]: b*1024 + i   (holds h0(t-1))
    float* h1s = sm + IDIM * 8;         //                      (holds h1(t-2))
    float* pf  = sm + IDIM * 16;        // A partials [warp][32]; B partials at +256

    int tid  = threadIdx.x;
    int lane = tid & 31;
    int warp = tid >> 5;
    int row0 = blockIdx.x * 8;

    uint32_t h0sa = (uint32_t)__cvta_generic_to_shared(h0s);
    uint32_t h1sa = (uint32_t)__cvta_generic_to_shared(h1s);

    // ---- A-part mapping (Whh0 on h0prev, Whh1 on h1prev2): warp = mat + 2*g + 4*kc ----
    int matA = warp & 1;
    int gA   = (warp >> 1) & 1;
    int kcA  = warp >> 2;               // 0..1, K-chunk of 512
    const float* WA = matA ? Whh1 : Whh0;
    float* hA = matA ? h1s : h0s;
    int kbA = kcA * 512;
    float4 wAreg[4][4];
#pragma unroll
    for (int grp = 0; grp < 4; grp++)
#pragma unroll
        for (int r = 0; r < 4; r++)
            wAreg[grp][r] = *(const float4*)&WA[(size_t)(row0 + gA * 4 + r) * IDIM
                                                + kbA + grp * 128 + lane * 4];

    // ---- B-part mapping (Wih1 on h0prev): warp = g + 2*kc ----
    int gB  = warp & 1;
    int kcB = warp >> 1;                // 0..3, K-chunk of 256
    int kbB = kcB * 256;
    float4 wBreg[2][4];
#pragma unroll
    for (int grp = 0; grp < 2; grp++)
#pragma unroll
        for (int r = 0; r < 4; r++)
            wBreg[grp][r] = *(const float4*)&Wih1[(size_t)(row0 + gB * 4 + r) * IDIM
                                                  + kbB + grp * 128 + lane * 4];

    // combine-thread params: b = tid&7, jl = (tid&63)>>3, j = row0+jl
    int cmb_b  = tid & 7;
    int cmb_jl = (tid & 63) >> 3;
    int cmb_j  = row0 + cmb_jl;
    float cbias = 0.0f;
    if (tid >= 64 && tid < 128) cbias = bih1[cmb_j] + bhh1[cmb_j];

    // ---- prefill exchange buffers with starter state ----
    if (tid < 64) {
        float s0 = starter[cmb_j];
        float s1 = starter[IDIM + cmb_j];
        g_h0x[1][cmb_b * IDIM + cmb_j] = s0;
        g_h1x[0][cmb_b * IDIM + cmb_j] = s1;
        g_h1x[1][cmb_b * IDIM + cmb_j] = s1;
    }
    unsigned epoch = 1;
    tree_sync(epoch++);

    // ================= main loop: slot t computes h0(t) and h1(t-1) =================
    for (int t = 0; t <= TLEN; t++) {
        // async broadcast-in: h0(t-1) [group 0], h1(t-2) [group 1]
        {
            const float4* s0 = (const float4*)g_h0x[(t + 1) & 1];
            const float4* s1 = (const float4*)g_h1x[t & 1];
#pragma unroll
            for (int q = 0; q < 8; q++)
                cp_async16(h0sa + (unsigned)(tid + q * 256) * 16u, s0 + tid + q * 256);
            CP_COMMIT();
#pragma unroll
            for (int q = 0; q < 8; q++)
                cp_async16(h1sa + (unsigned)(tid + q * 256) * 16u, s1 + tid + q * 256);
            CP_COMMIT();
        }

        // U0 prefetch for h0(t) (hidden under the dots)
        float u0v = 0.0f;
        if (tid < 64 && t < TLEN)
            u0v = __ldcg(&U0[(size_t)t * (BATCH * IDIM) + (size_t)cmb_b * IDIM + cmb_j]);

        CP_WAIT1();             // h0 group done (h1 still in flight)
        __syncthreads();

        // ---------- B dots first (need only h0): Wih1 h0prev, 4r x 8b x K256 --------
        {
            float acc[32];
#pragma unroll
            for (int v = 0; v < 32; v++) acc[v] = 0.0f;
#pragma unroll
            for (int grp = 0; grp < 2; grp++) {
                int ib = kbB + grp * 128 + lane * 4;
                float4 h[8];
#pragma unroll
                for (int b = 0; b < 8; b++) h[b] = *(const float4*)&h0s[b * 1024 + ib];
#pragma unroll
                for (int r = 0; r < 4; r++) {
                    float4 wv = wBreg[grp][r];
#pragma unroll
                    for (int b = 0; b < 8; b++) {
                        acc[r * 8 + b] += wv.x * h[b].x;
                        acc[r * 8 + b] += wv.y * h[b].y;
                        acc[r * 8 + b] += wv.z * h[b].z;
                        acc[r * 8 + b] += wv.w * h[b].w;
                    }
                }
            }
            pf[256 + warp * 32 + lane] = bfly_reduce32(acc, lane);
        }

        CP_WAIT0();             // h1 group done
        __syncthreads();

        // ---------- A dots: {Whh0 h0prev | Whh1 h1prev2}, 4r x 8b x K512 ----------
        {
            float acc[32];
#pragma unroll
            for (int v = 0; v < 32; v++) acc[v] = 0.0f;
#pragma unroll
            for (int grp = 0; grp < 4; grp++) {
                int ib = kbA + grp * 128 + lane * 4;
                float4 h[8];
#pragma unroll
                for (int b = 0; b < 8; b++) h[b] = *(const float4*)&hA[b * 1024 + ib];
#pragma unroll
                for (int r = 0; r < 4; r++) {
                    float4 wv = wAreg[grp][r];
#pragma unroll
                    for (int b = 0; b < 8; b++) {
                        acc[r * 8 + b] += wv.x * h[b].x;
                        acc[r * 8 + b] += wv.y * h[b].y;
                        acc[r * 8 + b] += wv.z * h[b].z;
                        acc[r * 8 + b] += wv.w * h[b].w;
                    }
                }
            }
            pf[warp * 32 + lane] = bfly_reduce32(acc, lane);
        }
        __syncthreads();

        // ---------- combine ----------
        if (tid < 64) {
            // h0(t) = tanh(u0(t) + Whh0 h0(t-1))
            if (t < TLEN) {
                int g = cmb_jl >> 2, r = cmb_jl & 3;
                int fidx = r * 8 + cmb_b;
                float s = pf[(0 + 2 * g) * 32 + fidx] + pf[(0 + 2 * g + 4) * 32 + fidx];
                float hv = tanhf(u0v + s);
                g_h0x[t & 1][cmb_b * IDIM + cmb_j] = hv;
            }
        } else if (tid < 128) {
            // h1(t-1) = tanh(Whh1 h1(t-2) + Wih1 h0(t-1) + biases)
            if (t >= 1) {
                int g = cmb_jl >> 2, r = cmb_jl & 3;
                int fidx = r * 8 + cmb_b;
                float sA = pf[(1 + 2 * g) * 32 + fidx] + pf[(1 + 2 * g + 4) * 32 + fidx];
                float sB = pf[256 + (g + 0) * 32 + fidx] + pf[256 + (g + 2) * 32 + fidx]
                         + pf[256 + (g + 4) * 32 + fidx] + pf[256 + (g + 6) * 32 + fidx];
                float hv = tanhf(sA + sB + cbias);
                g_h1x[(t + 1) & 1][cmb_b * IDIM + cmb_j] = hv;
                Y[((size_t)cmb_b * TLEN + (t - 1)) * IDIM + cmb_j] = hv;
            }
        }

        tree_sync(epoch++);
    }
}

// ---------------- launch ----------------
extern "C" void kernel_launch(void* const* d_in, const int* in_sizes, int n_in,
                              void* d_out, int out_size)
{
    const float* x      = (const float*)d_in[0];
    const float* w_dw0  = (const float*)d_in[1];
    const float* b_dw0  = (const float*)d_in[2];
    const float* w_dw1  = (const float*)d_in[3];
    const float* b_dw1  = (const float*)d_in[4];
    const float* w_join = (const float*)d_in[5];
    const float* b_join = (const float*)d_in[6];
    const float* w_ih0  = (const float*)d_in[7];
    const float* w_hh0  = (const float*)d_in[8];
    const float* b_ih0  = (const float*)d_in[9];
    const float* b_hh0  = (const float*)d_in[10];
    const float* w_ih1  = (const float*)d_in[11];
    const float* w_hh1  = (const float*)d_in[12];
    const float* b_ih1  = (const float*)d_in[13];
    const float* b_hh1  = (const float*)d_in[14];
    const float* w_u1   = (const float*)d_in[15];
    const float* b_u1   = (const float*)d_in[16];
    const float* w_u2   = (const float*)d_in[17];
    const float* b_u2   = (const float*)d_in[18];
    const float* starter= (const float*)d_in[19];
    float* out = (float*)d_out;

    float *H, *Z, *U0, *Yr, *Y2, *Y3;
    cudaGetSymbolAddress((void**)&H,  g_H);
    cudaGetSymbolAddress((void**)&Z,  g_Z);
    cudaGetSymbolAddress((void**)&U0, g_U0);
    cudaGetSymbolAddress((void**)&Yr, g_Yr);
    cudaGetSymbolAddress((void**)&Y2, g_Y2);
    cudaGetSymbolAddress((void**)&Y3, g_Y3);

    // 0) reset RNN tree-barrier counters (graph replays reuse device globals)
    zero_tree_kernel<<<1, 512>>>();

    // 1) dwconv0 + gelu -> H [b][d][t]
    dwconv_kernel<<<BATCH * DIMC, 256>>>(x, w_dw0, b_dw0, nullptr, H, 1);

    // 2) join: Z[b][t][i] = H[b][:,t] . w_join[i,:] + b_join
    sgemm_kernel<true, false, false><<<dim3(IDIM / BN, TLEN / BM, BATCH), 256>>>(
        H, w_join, b_join, nullptr, Z,
        TLEN, IDIM, DIMC, TLEN, (long)DIMC * TLEN, (long)TLEN * IDIM, IDIM);

    // 3) u0: U0[t][b][j] = Z[b][t][:] . w_ih0[j,:] + b_ih0 + b_hh0
    sgemm_kernel<false, false, false><<<dim3(IDIM / BN, TLEN / BM, BATCH), 256>>>(
        Z, w_ih0, b_ih0, b_hh0, U0,
        TLEN, IDIM, IDIM, IDIM, (long)TLEN * IDIM, (long)IDIM, BATCH * IDIM);

    // 4) persistent RNN over T steps -> Yr [b][t][j]
    cudaFuncSetAttribute(rnn_kernel, cudaFuncAttributeMaxDynamicSharedMemorySize,
                         RNN_SMEM_FLOATS * (int)sizeof(float));
    rnn_kernel<<<NC, 256, RNN_SMEM_FLOATS * (int)sizeof(float)>>>(
        U0, w_hh0, w_ih1, w_hh1, b_ih1, b_hh1, starter, Yr);

    // 5) u1 + gelu
    sgemm_kernel<false, true, false><<<dim3(IDIM / BN, TLEN / BM, BATCH), 256>>>(
        Yr, w_u1, b_u1, nullptr, Y2,
        TLEN, IDIM, IDIM, IDIM, (long)TLEN * IDIM, (long)TLEN * IDIM, IDIM);

    // 6) u2 + gelu, transposed store: Y3[b][d][t]
    sgemm_kernel<false, true, true><<<dim3(DIMC / BN, TLEN / BM, BATCH), 256>>>(
        Y2, w_u2, b_u2, nullptr, Y3,
        TLEN, DIMC, IDIM, IDIM, (long)TLEN * IDIM, (long)DIMC * TLEN, TLEN);

    // 7) dwconv1 + bias + residual -> out [b][d][t]
    dwconv_kernel<<<BATCH * DIMC, 256>>>(Y3, w_dw1, b_dw1, x, out, 0);
}